// round 16
// baseline (speedup 1.0000x reference)
#include <cuda_runtime.h>
#include <cuda_fp16.h>
#include <cstddef>
#include <cstdint>

#define VOCAB 100000
#define NB    16384
#define LSEQ  200
#define EMB   128
#define NCLS  1000

// Scratch (alloc-free rule: __device__ globals).
__device__ __align__(16) __half g_table_h[(size_t)VOCAB * EMB];   // 25.6 MB
__device__ __align__(16) __half g_w_h[(size_t)NCLS * EMB];        // 256 KB
__device__ __align__(16) __half g_pooled_h[(size_t)NB * EMB];     // 4 MB

// ---------------------------------------------------------------------------
// Stage 0: convert table AND fc_w fp32 -> fp16 — proven version (12.2 us).
// ---------------------------------------------------------------------------
#define N_TBL4 ((size_t)VOCAB * EMB / 4)
#define N_W4   ((size_t)NCLS * EMB / 4)
#define N_ALL4 (N_TBL4 + N_W4)

__global__ __launch_bounds__(256) void convert_kernel(const float* __restrict__ t,
                                                      const float* __restrict__ W) {
    const size_t base = (size_t)blockIdx.x * 1024 + threadIdx.x;
    float4 v[4];
    bool   ok[4];
    #pragma unroll
    for (int i = 0; i < 4; ++i) {
        const size_t idx = base + (size_t)i * 256;
        ok[i] = idx < N_ALL4;
        if (ok[i])
            v[i] = (idx < N_TBL4) ? reinterpret_cast<const float4*>(t)[idx]
                                  : reinterpret_cast<const float4*>(W)[idx - N_TBL4];
    }
    #pragma unroll
    for (int i = 0; i < 4; ++i) {
        if (!ok[i]) continue;
        const size_t idx = base + (size_t)i * 256;
        union { __half2 h[2]; uint2 u; } pk;
        pk.h[0] = __floats2half2_rn(v[i].x, v[i].y);
        pk.h[1] = __floats2half2_rn(v[i].z, v[i].w);
        if (idx < N_TBL4) reinterpret_cast<uint2*>(g_table_h)[idx] = pk.u;
        else              reinterpret_cast<uint2*>(g_w_h)[idx - N_TBL4] = pk.u;
    }
}

// ---------------------------------------------------------------------------
// Stage 1: pool in R1's MEMORY SHAPE (the only shape that sustained
// 15.8 TB/s) with fp16 data: each warp request is LDG.32 x 32 lanes = 128 B
// = EXACTLY ONE cache line. Two warps per row (64 dims each as half2),
// 4 rows per 256-thread block. Same 4-accumulator fp32 structure and token
// order as R3 -> per-dim arithmetic bit-identical.
// ---------------------------------------------------------------------------
__device__ __forceinline__ void hacc2(float2& a, uint32_t u) {
    const float2 f = __half22float2(*reinterpret_cast<__half2*>(&u));
    a.x += f.x; a.y += f.y;
}

__global__ __launch_bounds__(256) void pool_kernel(const int* __restrict__ seq) {
    __shared__ int s_tok[4][LSEQ];
    const int wid  = threadIdx.x >> 5;     // 0..7
    const int lane = threadIdx.x & 31;
    const int rw   = wid >> 1;             // row within block: 0..3
    const int half = wid & 1;              // dim half: 0 or 1
    const int b0   = blockIdx.x * 4;

    for (int i = threadIdx.x; i < 4 * LSEQ; i += 256)
        s_tok[i / LSEQ][i % LSEQ] = seq[(size_t)b0 * LSEQ + i];
    __syncthreads();

    // Lane's half2 slot within the row (uint units of the fp16 row).
    const int slot = half * 32 + lane;     // 0..63
    const uint32_t* tbl = reinterpret_cast<const uint32_t*>(g_table_h) + slot;

    float2 a0 = {0,0}, a1 = {0,0}, a2 = {0,0}, a3 = {0,0};

    #pragma unroll 2
    for (int l = 0; l < LSEQ; l += 4) {
        const int t0 = s_tok[rw][l + 0];
        const int t1 = s_tok[rw][l + 1];
        const int t2 = s_tok[rw][l + 2];
        const int t3 = s_tok[rw][l + 3];
        if (t0) hacc2(a0, tbl[(size_t)t0 * 64]);   // EMB/2 = 64 uints per row
        if (t1) hacc2(a1, tbl[(size_t)t1 * 64]);
        if (t2) hacc2(a2, tbl[(size_t)t2 * 64]);
        if (t3) hacc2(a3, tbl[(size_t)t3 * 64]);
    }

    const float rx = (a0.x + a1.x) + (a2.x + a3.x);
    const float ry = (a0.y + a1.y) + (a2.y + a3.y);
    const __half2 h = __floats2half2_rn(rx, ry);

    reinterpret_cast<uint32_t*>(g_pooled_h)[(size_t)(b0 + rw) * 64 + slot] =
        *reinterpret_cast<const uint32_t*>(&h);
}

// ---------------------------------------------------------------------------
// Stage 2: HMMA GEMM — EXACT R15 version (register-prefetched B, __stcs
// epilogue; measured identical to the R7 floor).
// ---------------------------------------------------------------------------
__device__ __forceinline__ void mma16816(float* d,
                                         uint32_t a0, uint32_t a1, uint32_t a2, uint32_t a3,
                                         uint32_t b0, uint32_t b1) {
    asm volatile(
        "mma.sync.aligned.m16n8k16.row.col.f32.f16.f16.f32 "
        "{%0,%1,%2,%3}, {%4,%5,%6,%7}, {%8,%9}, {%0,%1,%2,%3};\n"
        : "+f"(d[0]), "+f"(d[1]), "+f"(d[2]), "+f"(d[3])
        : "r"(a0), "r"(a1), "r"(a2), "r"(a3), "r"(b0), "r"(b1));
}

__device__ __forceinline__ int swz(int row, int chunk) {
    return row * 128 + ((chunk ^ (row & 7)) << 3);
}

__global__ __launch_bounds__(256) void gemm_kernel(const float* __restrict__ bias,
                                                   float* __restrict__ out) {
    __shared__ __half sA[128 * 128];   // 32 KB
    __shared__ __half sB[64 * 128];    // 16 KB

    const int tid  = threadIdx.x;
    const int lane = tid & 31;
    const int wid  = tid >> 5;
    const int wm   = wid >> 1;
    const int wn   = wid & 1;
    const int m0   = blockIdx.x * 128;
    const int nb0  = blockIdx.y * 128;

    const int lq = lane >> 2;
    const int lr = lane & 3;
    const int r0 = tid >> 4;
    const int c  = tid & 15;

    uint4 vb[4];
    #pragma unroll
    for (int it = 0; it < 4; ++it) {
        const int r = r0 + it * 16;
        vb[it] = (nb0 + r < NCLS)
            ? reinterpret_cast<const uint4*>(g_w_h + (size_t)(nb0 + r) * EMB)[c]
            : make_uint4(0u, 0u, 0u, 0u);
    }
    #pragma unroll
    for (int it = 0; it < 8; ++it) {
        const int r = r0 + it * 16;
        const uint4 v = reinterpret_cast<const uint4*>(
            g_pooled_h + (size_t)(m0 + r) * EMB)[c];
        *reinterpret_cast<uint4*>(&sA[swz(r, c)]) = v;
    }

    #pragma unroll
    for (int p = 0; p < 2; ++p) {
        const int n0 = nb0 + p * 64;

        if (p) __syncthreads();
        #pragma unroll
        for (int it = 0; it < 4; ++it)
            *reinterpret_cast<uint4*>(&sB[swz(r0 + it * 16, c)]) = vb[it];

        if (p == 0) {
            #pragma unroll
            for (int it = 0; it < 4; ++it) {
                const int r = r0 + it * 16;
                vb[it] = (nb0 + 64 + r < NCLS)
                    ? reinterpret_cast<const uint4*>(
                          g_w_h + (size_t)(nb0 + 64 + r) * EMB)[c]
                    : make_uint4(0u, 0u, 0u, 0u);
            }
        }

        __syncthreads();

        float2 bpre[4];
        #pragma unroll
        for (int nt = 0; nt < 4; ++nt) {
            const int n = n0 + wn * 32 + nt * 8 + lr * 2;
            bpre[nt] = (n < NCLS) ? *reinterpret_cast<const float2*>(bias + n)
                                  : make_float2(0.f, 0.f);
        }

        float acc[2][4][4] = {};

        #pragma unroll
        for (int ks = 0; ks < 8; ++ks) {
            uint32_t a[2][4];
            #pragma unroll
            for (int mi = 0; mi < 2; ++mi) {
                const int r  = wm * 32 + mi * 16 + lq;
                const int o0 = ((2 * ks)     ^ (r & 7)) * 8 + lr * 2;
                const int o1 = ((2 * ks + 1) ^ (r & 7)) * 8 + lr * 2;
                a[mi][0] = *reinterpret_cast<const uint32_t*>(&sA[r * 128 + o0]);
                a[mi][1] = *reinterpret_cast<const uint32_t*>(&sA[(r + 8) * 128 + o0]);
                a[mi][2] = *reinterpret_cast<const uint32_t*>(&sA[r * 128 + o1]);
                a[mi][3] = *reinterpret_cast<const uint32_t*>(&sA[(r + 8) * 128 + o1]);
            }
            #pragma unroll
            for (int nt = 0; nt < 4; ++nt) {
                const int n  = wn * 32 + nt * 8 + lq;
                const int o0 = ((2 * ks)     ^ (n & 7)) * 8 + lr * 2;
                const int o1 = ((2 * ks + 1) ^ (n & 7)) * 8 + lr * 2;
                const uint32_t b0 = *reinterpret_cast<const uint32_t*>(&sB[n * 128 + o0]);
                const uint32_t b1 = *reinterpret_cast<const uint32_t*>(&sB[n * 128 + o1]);
                #pragma unroll
                for (int mi = 0; mi < 2; ++mi)
                    mma16816(acc[mi][nt], a[mi][0], a[mi][1], a[mi][2], a[mi][3], b0, b1);
            }
        }

        #pragma unroll
        for (int nt = 0; nt < 4; ++nt) {
            const int n = n0 + wn * 32 + nt * 8 + lr * 2;
            if (n < NCLS) {
                #pragma unroll
                for (int mi = 0; mi < 2; ++mi) {
                    const int m = m0 + wm * 32 + mi * 16 + lq;
                    float2 s0, s1;
                    s0.x = acc[mi][nt][0] + bpre[nt].x;
                    s0.y = acc[mi][nt][1] + bpre[nt].y;
                    s1.x = acc[mi][nt][2] + bpre[nt].x;
                    s1.y = acc[mi][nt][3] + bpre[nt].y;
                    __stcs(reinterpret_cast<float2*>(out + (size_t)m * NCLS + n), s0);
                    __stcs(reinterpret_cast<float2*>(out + (size_t)(m + 8) * NCLS + n), s1);
                }
            }
        }
    }
}

extern "C" void kernel_launch(void* const* d_in, const int* in_sizes, int n_in,
                              void* d_out, int out_size) {
    const int*   seq   = (const int*)d_in[0];
    const float* table = (const float*)d_in[1];
    const float* W     = (const float*)d_in[2];
    const float* bias  = (const float*)d_in[3];
    float*       out   = (float*)d_out;

    const int conv_blocks = (int)((N_ALL4 + 1023) / 1024);
    convert_kernel<<<conv_blocks, 256>>>(table, W);

    pool_kernel<<<NB / 4, 256>>>(seq);

    dim3 grid(NB / 128, (NCLS + 127) / 128);
    gemm_kernel<<<grid, 256>>>(bias, out);
}

// round 17
// speedup vs baseline: 1.0864x; 1.0864x over previous
#include <cuda_runtime.h>
#include <cuda_fp16.h>
#include <cstddef>
#include <cstdint>

#define VOCAB 100000
#define NB    16384
#define LSEQ  200
#define EMB   128
#define NCLS  1000

// Scratch (alloc-free rule: __device__ globals).
__device__ __align__(16) __half g_table_h[(size_t)VOCAB * EMB];   // 25.6 MB
__device__ __align__(16) __half g_w_h[(size_t)NCLS * EMB];        // 256 KB
__device__ __align__(16) __half g_pooled_h[(size_t)NB * EMB];     // 4 MB

// ---------------------------------------------------------------------------
// Stage 0: convert table AND fc_w fp32 -> fp16.
// At the DRAM-read floor (12.2 us; profiled 8x). MLP_p1 = 4, regs 28.
// fp16 halves the pool's gather traffic; quantization (~2e-4 rms) is the
// dominant and acceptable error term (budget 1e-3).
// ---------------------------------------------------------------------------
#define N_TBL4 ((size_t)VOCAB * EMB / 4)
#define N_W4   ((size_t)NCLS * EMB / 4)
#define N_ALL4 (N_TBL4 + N_W4)

__global__ __launch_bounds__(256) void convert_kernel(const float* __restrict__ t,
                                                      const float* __restrict__ W) {
    const size_t base = (size_t)blockIdx.x * 1024 + threadIdx.x;
    float4 v[4];
    bool   ok[4];
    #pragma unroll
    for (int i = 0; i < 4; ++i) {
        const size_t idx = base + (size_t)i * 256;
        ok[i] = idx < N_ALL4;
        if (ok[i])
            v[i] = (idx < N_TBL4) ? reinterpret_cast<const float4*>(t)[idx]
                                  : reinterpret_cast<const float4*>(W)[idx - N_TBL4];
    }
    #pragma unroll
    for (int i = 0; i < 4; ++i) {
        if (!ok[i]) continue;
        const size_t idx = base + (size_t)i * 256;
        union { __half2 h[2]; uint2 u; } pk;
        pk.h[0] = __floats2half2_rn(v[i].x, v[i].y);
        pk.h[1] = __floats2half2_rn(v[i].z, v[i].w);
        if (idx < N_TBL4) reinterpret_cast<uint2*>(g_table_h)[idx] = pk.u;
        else              reinterpret_cast<uint2*>(g_w_h)[idx - N_TBL4] = pk.u;
    }
}

// ---------------------------------------------------------------------------
// Stage 1: masked embedding-bag sum pool. One warp per batch row; lane owns
// 4 dims (uint2 = half4 loads); fp32 accumulate; fp16 output.
// At the chip's aggregate-L2 gather bound (~68 us for 840 MB) — invariant
// to LDG width (R10), L1 policy (R8), slice hashing (R11), and warp shape
// (R16); requires the whole chip (overlap falsified R5/R6/R13).
// ---------------------------------------------------------------------------
__device__ __forceinline__ void hacc(float4& a, uint2 u) {
    const float2 f0 = __half22float2(*reinterpret_cast<__half2*>(&u.x));
    const float2 f1 = __half22float2(*reinterpret_cast<__half2*>(&u.y));
    a.x += f0.x; a.y += f0.y; a.z += f1.x; a.w += f1.y;
}

__global__ __launch_bounds__(256) void pool_kernel(const int* __restrict__ seq) {
    __shared__ int s_tok[8][LSEQ];
    const int wid  = threadIdx.x >> 5;
    const int lane = threadIdx.x & 31;
    const int b0   = blockIdx.x * 8;

    for (int i = threadIdx.x; i < 8 * LSEQ; i += 256)
        s_tok[i / LSEQ][i % LSEQ] = seq[(size_t)b0 * LSEQ + i];
    __syncthreads();

    float4 a0 = {0,0,0,0}, a1 = {0,0,0,0}, a2 = {0,0,0,0}, a3 = {0,0,0,0};

    #pragma unroll 2
    for (int l = 0; l < LSEQ; l += 4) {
        const int t0 = s_tok[wid][l + 0];
        const int t1 = s_tok[wid][l + 1];
        const int t2 = s_tok[wid][l + 2];
        const int t3 = s_tok[wid][l + 3];
        if (t0) hacc(a0, reinterpret_cast<const uint2*>(g_table_h + (size_t)t0 * EMB)[lane]);
        if (t1) hacc(a1, reinterpret_cast<const uint2*>(g_table_h + (size_t)t1 * EMB)[lane]);
        if (t2) hacc(a2, reinterpret_cast<const uint2*>(g_table_h + (size_t)t2 * EMB)[lane]);
        if (t3) hacc(a3, reinterpret_cast<const uint2*>(g_table_h + (size_t)t3 * EMB)[lane]);
    }

    union { __half2 h[2]; uint2 u; } pk;
    pk.h[0] = __floats2half2_rn((a0.x + a1.x) + (a2.x + a3.x),
                                (a0.y + a1.y) + (a2.y + a3.y));
    pk.h[1] = __floats2half2_rn((a0.z + a1.z) + (a2.z + a3.z),
                                (a0.w + a1.w) + (a2.w + a3.w));
    reinterpret_cast<uint2*>(g_pooled_h + (size_t)(b0 + wid) * EMB)[lane] = pk.u;
}

// ---------------------------------------------------------------------------
// Stage 2: HMMA GEMM (store-bound floor ~16 us). Block computes 128x128
// output via two 64-wide n-passes sharing one A tile; pass-1 B register-
// prefetched under pass-0 compute; __stcs epilogue keeps L2 for pooled/W.
// 8 warps as 4(m) x 2(n); warp tile 32x32; K=128 resident; XOR swizzle.
// ---------------------------------------------------------------------------
__device__ __forceinline__ void mma16816(float* d,
                                         uint32_t a0, uint32_t a1, uint32_t a2, uint32_t a3,
                                         uint32_t b0, uint32_t b1) {
    asm volatile(
        "mma.sync.aligned.m16n8k16.row.col.f32.f16.f16.f32 "
        "{%0,%1,%2,%3}, {%4,%5,%6,%7}, {%8,%9}, {%0,%1,%2,%3};\n"
        : "+f"(d[0]), "+f"(d[1]), "+f"(d[2]), "+f"(d[3])
        : "r"(a0), "r"(a1), "r"(a2), "r"(a3), "r"(b0), "r"(b1));
}

__device__ __forceinline__ int swz(int row, int chunk) {
    return row * 128 + ((chunk ^ (row & 7)) << 3);
}

__global__ __launch_bounds__(256) void gemm_kernel(const float* __restrict__ bias,
                                                   float* __restrict__ out) {
    __shared__ __half sA[128 * 128];   // 32 KB
    __shared__ __half sB[64 * 128];    // 16 KB

    const int tid  = threadIdx.x;
    const int lane = tid & 31;
    const int wid  = tid >> 5;
    const int wm   = wid >> 1;
    const int wn   = wid & 1;
    const int m0   = blockIdx.x * 128;
    const int nb0  = blockIdx.y * 128;

    const int lq = lane >> 2;
    const int lr = lane & 3;
    const int r0 = tid >> 4;
    const int c  = tid & 15;

    uint4 vb[4];
    #pragma unroll
    for (int it = 0; it < 4; ++it) {
        const int r = r0 + it * 16;
        vb[it] = (nb0 + r < NCLS)
            ? reinterpret_cast<const uint4*>(g_w_h + (size_t)(nb0 + r) * EMB)[c]
            : make_uint4(0u, 0u, 0u, 0u);
    }
    #pragma unroll
    for (int it = 0; it < 8; ++it) {
        const int r = r0 + it * 16;
        const uint4 v = reinterpret_cast<const uint4*>(
            g_pooled_h + (size_t)(m0 + r) * EMB)[c];
        *reinterpret_cast<uint4*>(&sA[swz(r, c)]) = v;
    }

    #pragma unroll
    for (int p = 0; p < 2; ++p) {
        const int n0 = nb0 + p * 64;

        if (p) __syncthreads();
        #pragma unroll
        for (int it = 0; it < 4; ++it)
            *reinterpret_cast<uint4*>(&sB[swz(r0 + it * 16, c)]) = vb[it];

        if (p == 0) {
            #pragma unroll
            for (int it = 0; it < 4; ++it) {
                const int r = r0 + it * 16;
                vb[it] = (nb0 + 64 + r < NCLS)
                    ? reinterpret_cast<const uint4*>(
                          g_w_h + (size_t)(nb0 + 64 + r) * EMB)[c]
                    : make_uint4(0u, 0u, 0u, 0u);
            }
        }

        __syncthreads();

        float2 bpre[4];
        #pragma unroll
        for (int nt = 0; nt < 4; ++nt) {
            const int n = n0 + wn * 32 + nt * 8 + lr * 2;
            bpre[nt] = (n < NCLS) ? *reinterpret_cast<const float2*>(bias + n)
                                  : make_float2(0.f, 0.f);
        }

        float acc[2][4][4] = {};

        #pragma unroll
        for (int ks = 0; ks < 8; ++ks) {
            uint32_t a[2][4];
            #pragma unroll
            for (int mi = 0; mi < 2; ++mi) {
                const int r  = wm * 32 + mi * 16 + lq;
                const int o0 = ((2 * ks)     ^ (r & 7)) * 8 + lr * 2;
                const int o1 = ((2 * ks + 1) ^ (r & 7)) * 8 + lr * 2;
                a[mi][0] = *reinterpret_cast<const uint32_t*>(&sA[r * 128 + o0]);
                a[mi][1] = *reinterpret_cast<const uint32_t*>(&sA[(r + 8) * 128 + o0]);
                a[mi][2] = *reinterpret_cast<const uint32_t*>(&sA[r * 128 + o1]);
                a[mi][3] = *reinterpret_cast<const uint32_t*>(&sA[(r + 8) * 128 + o1]);
            }
            #pragma unroll
            for (int nt = 0; nt < 4; ++nt) {
                const int n  = wn * 32 + nt * 8 + lq;
                const int o0 = ((2 * ks)     ^ (n & 7)) * 8 + lr * 2;
                const int o1 = ((2 * ks + 1) ^ (n & 7)) * 8 + lr * 2;
                const uint32_t b0 = *reinterpret_cast<const uint32_t*>(&sB[n * 128 + o0]);
                const uint32_t b1 = *reinterpret_cast<const uint32_t*>(&sB[n * 128 + o1]);
                #pragma unroll
                for (int mi = 0; mi < 2; ++mi)
                    mma16816(acc[mi][nt], a[mi][0], a[mi][1], a[mi][2], a[mi][3], b0, b1);
            }
        }

        #pragma unroll
        for (int nt = 0; nt < 4; ++nt) {
            const int n = n0 + wn * 32 + nt * 8 + lr * 2;
            if (n < NCLS) {
                #pragma unroll
                for (int mi = 0; mi < 2; ++mi) {
                    const int m = m0 + wm * 32 + mi * 16 + lq;
                    float2 s0, s1;
                    s0.x = acc[mi][nt][0] + bpre[nt].x;
                    s0.y = acc[mi][nt][1] + bpre[nt].y;
                    s1.x = acc[mi][nt][2] + bpre[nt].x;
                    s1.y = acc[mi][nt][3] + bpre[nt].y;
                    __stcs(reinterpret_cast<float2*>(out + (size_t)m * NCLS + n), s0);
                    __stcs(reinterpret_cast<float2*>(out + (size_t)(m + 8) * NCLS + n), s1);
                }
            }
        }
    }
}

extern "C" void kernel_launch(void* const* d_in, const int* in_sizes, int n_in,
                              void* d_out, int out_size) {
    const int*   seq   = (const int*)d_in[0];
    const float* table = (const float*)d_in[1];
    const float* W     = (const float*)d_in[2];
    const float* bias  = (const float*)d_in[3];
    float*       out   = (float*)d_out;

    const int conv_blocks = (int)((N_ALL4 + 1023) / 1024);
    convert_kernel<<<conv_blocks, 256>>>(table, W);

    pool_kernel<<<NB / 8, 256>>>(seq);

    dim3 grid(NB / 128, (NCLS + 127) / 128);
    gemm_kernel<<<grid, 256>>>(bias, out);
}